// round 6
// baseline (speedup 1.0000x reference)
#include <cuda_runtime.h>
#include <cstdint>

#define VOCAB 50257
#define DIM 1024
#define COLS4 (DIM / 4)
#define BLANK_TOKEN_ID 100
#define B 4
#define S 4096
#define NROWS (B * S)
#define BATCH 4
#define NCTAS 1216   // ~8 CTAs/SM on 152-SM GB300 -> single wave

__global__ __launch_bounds__(256, 8)
void blank_embedding_kernel(const int* __restrict__ x,
                            const float* __restrict__ emb,
                            float* __restrict__ out)
{
    const int tid = threadIdx.x;

    // Blocked single-wave partition: CTA b owns rows [b*per, b*per+per)
    const int per     = (NROWS + NCTAS - 1) / NCTAS;   // 14
    const int row0    = blockIdx.x * per;
    const int row_end = min(row0 + per, NROWS);

    const float4* emb4 = reinterpret_cast<const float4*>(emb);
    float4* out4       = reinterpret_cast<float4*>(out);

    for (int base = row0; base < row_end; base += BATCH) {
        const int nb = min(BATCH, row_end - base);   // uniform within CTA

        int   tok[BATCH];
        float4 acc[BATCH];

        // Phase 1: issue all independent gathers back-to-back (MLP ~ nb)
#pragma unroll
        for (int j = 0; j < BATCH; ++j) {
            if (j < nb) {
                int t0 = __ldg(&x[base + j]);
                if ((unsigned)t0 >= VOCAB) t0 = 0;
                tok[j] = t0;
                acc[j] = __ldg(&emb4[(size_t)t0 * COLS4 + tid]);
            }
        }

        // Phase 2: rare preblank contributions.
        // add from s-k iff x[s-k] != BLANK && x[s-k+1] == BLANK, k=1..3
#pragma unroll
        for (int j = 0; j < BATCH; ++j) {
            if (j < nb) {
                const int row = base + j;
                const int s   = row & (S - 1);
                const int t0  = tok[j];
                const int xm1 = (s >= 1) ? __ldg(&x[row - 1]) : 0;
                const int xm2 = (s >= 2) ? __ldg(&x[row - 2]) : 0;
                // any condition requires a blank at row, row-1, or row-2
                const bool anyb = (t0 == BLANK_TOKEN_ID) |
                                  (s >= 1 && xm1 == BLANK_TOKEN_ID) |
                                  (s >= 2 && xm2 == BLANK_TOKEN_ID);
                if (anyb) {   // ~never taken (p ~ 1e-4 per row)
                    if (s >= 1 && xm1 != BLANK_TOKEN_ID && t0 == BLANK_TOKEN_ID) {
                        int t = ((unsigned)xm1 < VOCAB) ? xm1 : 0;
                        const float4 v = __ldg(&emb4[(size_t)t * COLS4 + tid]);
                        acc[j].x += v.x; acc[j].y += v.y; acc[j].z += v.z; acc[j].w += v.w;
                    }
                    if (s >= 2 && xm2 != BLANK_TOKEN_ID && xm1 == BLANK_TOKEN_ID) {
                        int t = ((unsigned)xm2 < VOCAB) ? xm2 : 0;
                        const float4 v = __ldg(&emb4[(size_t)t * COLS4 + tid]);
                        acc[j].x += v.x; acc[j].y += v.y; acc[j].z += v.z; acc[j].w += v.w;
                    }
                    if (s >= 3) {
                        const int xm3 = __ldg(&x[row - 3]);
                        if (xm3 != BLANK_TOKEN_ID && xm2 == BLANK_TOKEN_ID) {
                            int t = ((unsigned)xm3 < VOCAB) ? xm3 : 0;
                            const float4 v = __ldg(&emb4[(size_t)t * COLS4 + tid]);
                            acc[j].x += v.x; acc[j].y += v.y; acc[j].z += v.z; acc[j].w += v.w;
                        }
                    }
                }
            }
        }

        // Phase 3: streaming stores (output never re-read)
#pragma unroll
        for (int j = 0; j < BATCH; ++j) {
            if (j < nb) {
                __stcs(&out4[(size_t)(base + j) * COLS4 + tid], acc[j]);
            }
        }
    }
}

extern "C" void kernel_launch(void* const* d_in, const int* in_sizes, int n_in,
                              void* d_out, int out_size)
{
    const int* x     = (const int*)d_in[0];     // [B, S] int32
    const float* emb = (const float*)d_in[1];   // [VOCAB, DIM] f32
    float* out       = (float*)d_out;           // [B, S, DIM] f32

    blank_embedding_kernel<<<NCTAS, 256>>>(x, emb, out);
}